// round 14
// baseline (speedup 1.0000x reference)
#include <cuda_runtime.h>
#include <cstdint>

#define BATCH   2048
#define TT      50
#define NNODES  23
#define FF      4
#define HH      64
#define FUT     10
#define BPC     4                 // batches per CTA
#define ROWS    (BPC*NNODES)      // 92
#define MPAD    96
#define THREADS 512
#define CS      132               // sC row stride (floats): 64 spa | 64 h | 4 pad
#define SS      68                // sSup row stride

// packed weights: [k2][g][p][4] = {w[2k2][2p], w[2k2][2p+1], w[2k2+1][2p], w[2k2+1][2p+1]}
#define SZ_WP   (64*3*32*4)       // 24576
#define SMEM_FLOATS (SZ_WP + MPAD*CS + MPAD*SS + ROWS*24 + ROWS*FF + 256 + 64 + 128 + 64 + 64 + 2048 + 32 + 128 + 4)

typedef unsigned long long u64;

__device__ __forceinline__ void fma2(u64& d, u64 a, u64 b) {
    asm("fma.rn.f32x2 %0, %1, %2, %0;" : "+l"(d) : "l"(a), "l"(b));
}
__device__ __forceinline__ float2 unpk(u64 v) {
    float2 r; asm("mov.b64 {%0, %1}, %2;" : "=f"(r.x), "=f"(r.y) : "l"(v)); return r;
}
__device__ __forceinline__ u64 dup2(float a) {
    u64 r; asm("mov.b64 %0, {%1, %1};" : "=l"(r) : "f"(a)); return r;
}
__device__ __forceinline__ float sigmoidf_(float x) {
    return __fdividef(1.f, 1.f + __expf(-x));
}
__device__ __forceinline__ float tanhf_(float x) {
    return __fdividef(2.f, 1.f + __expf(-2.f * x)) - 1.f;
}

// one K-half (64 k): A col = kb*4 (kb0=0 -> spa ; kb0=16 -> h cols 64..127).
// Packed weight row k2 = 2*kb+k2h covers k=2k2,2k2+1 (k<64 W_ih^T, k>=64 W_hh^T).
// aR/aZ accumulate across both halves; aN per-half. 6 rows x 2 j x 3 gates.
__device__ __forceinline__ void gemm_half(const float* __restrict__ sC,
                                          const float* __restrict__ sWp,
                                          const int rofs[6], int p4, int kb0,
                                          u64 aR[6], u64 aZ[6], u64 aN[6]) {
    for (int kb = kb0; kb < kb0 + 16; ++kb) {
        float4 a[6];
#pragma unroll
        for (int q = 0; q < 6; ++q)
            a[q] = *(const float4*)(sC + rofs[q] + kb*4);
#pragma unroll
        for (int k2h = 0; k2h < 2; ++k2h) {
            const int k2 = 2*kb + k2h;
            const float* bp = sWp + k2*384 + p4;
            ulonglong2 br2 = *(const ulonglong2*)(bp);
            ulonglong2 bz2 = *(const ulonglong2*)(bp + 128);
            ulonglong2 bn2 = *(const ulonglong2*)(bp + 256);
#pragma unroll
            for (int q = 0; q < 6; ++q) {
                float e = k2h ? a[q].z : a[q].x;
                float o = k2h ? a[q].w : a[q].y;
                u64 de = dup2(e), dd = dup2(o);
                fma2(aR[q], de, br2.x); fma2(aR[q], dd, br2.y);
                fma2(aZ[q], de, bz2.x); fma2(aZ[q], dd, bz2.y);
                fma2(aN[q], de, bn2.x); fma2(aN[q], dd, bn2.y);
            }
        }
    }
}

extern "C" __global__ void __launch_bounds__(THREADS, 1)
gwm_kernel(const float* __restrict__ x_seq, const float* __restrict__ adj_seq,
           const float* __restrict__ W_gcn, const float* __restrict__ b_gcn,
           const float* __restrict__ W_ih,  const float* __restrict__ W_hh,
           const float* __restrict__ b_ih,  const float* __restrict__ b_hh,
           const float* __restrict__ W_d1,  const float* __restrict__ b_d1,
           const float* __restrict__ W_d2,  const float* __restrict__ b_d2,
           float* __restrict__ out)
{
    extern __shared__ float sm[];
    float* sWp  = sm;                 // packed gate weights
    float* sC   = sWp  + SZ_WP;       // [96][132] : cols 0..63 spa, 64..127 h
    float* sSup = sC   + MPAD*CS;     // [96][68]
    float* sAdj = sSup + MPAD*SS;     // [r][24]
    float* sX   = sAdj + ROWS*24;
    float* sWg  = sX   + ROWS*FF;     // [j][4]
    float* sbg  = sWg  + 256;
    float* sbrz = sbg  + 64;          // b_ih+b_hh for j 0..127 (r,z)
    float* sbin = sbrz + 128;         // b_ih[128+j]
    float* sbhn = sbin + 64;          // b_hh[128+j]
    float* sWd1 = sbhn + 64;          // [q][64]
    float* sbd1 = sWd1 + 2048;
    float* sWd2 = sbd1 + 32;          // [f][32]
    float* sbd2 = sWd2 + 128;

    const int tid  = threadIdx.x;
    const int w    = tid >> 5;
    const int lane = tid & 31;
    const int b0   = blockIdx.x * BPC;

    // GEMM tile mapping: 16 warps = 2 M-halves (48 rows) x 8 j-groups
    const int wm = w >> 3;            // 0..1
    const int wn = w & 7;             // 0..7
    const int ml = lane & 7;          // 0..7
    const int ng = lane >> 3;         // 0..3
    const int p  = wn*4 + ng;         // j-pair 0..31
    const int p4 = p*4;
    const int jr = p*2;               // even j 0..62
    // 6 rows per thread, stride-8 interleaved (verified in R10)
    int rofs[6];
#pragma unroll
    for (int q = 0; q < 6; ++q) rofs[q] = (wm*48 + q*8 + ml)*CS;

    // ---- one-time setup ----
    for (int e = tid; e < SZ_WP; e += THREADS) {
        int k2   = e / 384;
        int rem  = e - k2*384;
        int g    = rem >> 7;          // 0..2
        int rem2 = rem & 127;
        int pp   = rem2 >> 2;         // 0..31
        int qq   = rem2 & 3;
        int j = 2*pp + (qq & 1);
        int k = 2*k2 + (qq >> 1);
        sWp[e] = (k < 64) ? W_ih[(g*64 + j)*64 + k]
                          : W_hh[(g*64 + j)*64 + (k - 64)];
    }
    for (int e = tid; e < 256;  e += THREADS) sWg[e]  = W_gcn[e];
    for (int e = tid; e < 2048; e += THREADS) sWd1[e] = W_d1[e];
    if (tid < 64)  sbg[tid]  = b_gcn[tid];
    if (tid < 128) sbrz[tid] = b_ih[tid] + b_hh[tid];
    if (tid >= 128 && tid < 192) sbin[tid-128] = b_ih[tid];
    if (tid >= 192 && tid < 256) sbhn[tid-192] = b_hh[tid-64];   // b_hh[128..191]
    if (tid < 32)  sbd1[tid] = b_d1[tid];
    if (tid < 128) sWd2[tid] = W_d2[tid];
    if (tid < 4)   sbd2[tid] = b_d2[tid];
    for (int e = tid; e < MPAD*CS; e += THREADS) sC[e] = 0.f;   // spa=0, h0=0
    __syncthreads();

    for (int t = 0; t < TT + FUT; ++t) {
        const bool hist = (t < TT);
        if (hist) {
            for (int e = tid; e < ROWS*NNODES; e += THREADS) {
                int bl = e / (NNODES*NNODES);
                int i  = e - bl*(NNODES*NNODES);
                int n  = i / NNODES, m = i - n*NNODES;
                sAdj[(bl*NNODES + n)*24 + m] =
                    adj_seq[((size_t)(b0+bl)*TT + t)*(NNODES*NNODES) + i];
            }
            for (int e = tid; e < ROWS*FF; e += THREADS) {
                int bl = e / (NNODES*FF);
                int i  = e - bl*(NNODES*FF);
                sX[e] = x_seq[((size_t)(b0+bl)*TT + t)*(NNODES*FF) + i];
            }
            __syncthreads();
        }

        // ---- phase 1: support = x @ Wg^T + bg ----
        for (int e = tid; e < ROWS*HH; e += THREADS) {
            int r = e >> 6, j = e & 63;
            const float* xp = sX + r*FF;
            float v = sbg[j];
            v = fmaf(xp[0], sWg[j*4+0], v);
            v = fmaf(xp[1], sWg[j*4+1], v);
            v = fmaf(xp[2], sWg[j*4+2], v);
            v = fmaf(xp[3], sWg[j*4+3], v);
            sSup[r*SS + j] = v;
        }
        __syncthreads();

        // ---- phase 2: spa = relu(adj @ support) -> sC[:, 0..63] ----
        {
            const int rh = lane >> 4, jq = lane & 15;
            for (int pp = w; pp < 46; pp += 16) {
                int r  = 2*pp + rh;                   // 0..91
                int bl = r / NNODES;
                const float* arow = sAdj + r*24;
                const float* supb = sSup + (bl*NNODES)*SS;
                u64 a0 = 0ull, a1 = 0ull;
#pragma unroll
                for (int m = 0; m < NNODES; ++m) {
                    u64 am = dup2(arow[m]);
                    ulonglong2 s = *(const ulonglong2*)(supb + m*SS + 4*jq);
                    fma2(a0, am, s.x);
                    fma2(a1, am, s.y);
                }
                float2 f0 = unpk(a0), f1 = unpk(a1);
                float4 o;
                o.x = fmaxf(f0.x, 0.f); o.y = fmaxf(f0.y, 0.f);
                o.z = fmaxf(f1.x, 0.f); o.w = fmaxf(f1.y, 0.f);
                *(float4*)(sC + r*CS + 4*jq) = o;
            }
        }
        __syncthreads();

        // ---- phase 3: gate GEMM ----
        u64 aR[6], aZ[6], aNlo[6], aNhi[6];
#pragma unroll
        for (int q = 0; q < 6; ++q) { aR[q]=0ull; aZ[q]=0ull; aNlo[q]=0ull; aNhi[q]=0ull; }

        gemm_half(sC, sWp, rofs, p4, 0,  aR, aZ, aNlo);  // spa @ W_ih^T
        gemm_half(sC, sWp, rofs, p4, 16, aR, aZ, aNhi);  // h   @ W_hh^T

        // ---- GRU epilogue (in registers) ----
        float hnew[6][2];
        {
            const float2 brz_r = *(const float2*)(sbrz + jr);
            const float2 brz_z = *(const float2*)(sbrz + 64 + jr);
            const float2 bin_n = *(const float2*)(sbin + jr);
            const float2 bhn_n = *(const float2*)(sbhn + jr);
#pragma unroll
            for (int q = 0; q < 6; ++q) {
                float2 rv = unpk(aR[q]);
                float2 zv = unpk(aZ[q]);
                float2 nI = unpk(aNlo[q]);
                float2 nH = unpk(aNhi[q]);
                float r0 = sigmoidf_(rv.x + brz_r.x);
                float r1 = sigmoidf_(rv.y + brz_r.y);
                float z0 = sigmoidf_(zv.x + brz_z.x);
                float z1 = sigmoidf_(zv.y + brz_z.y);
                float n0 = tanhf_(nI.x + bin_n.x + r0*(nH.x + bhn_n.x));
                float n1 = tanhf_(nI.y + bin_n.y + r1*(nH.y + bhn_n.y));
                float2 ho = *(const float2*)(sC + rofs[q] + 64 + jr);
                hnew[q][0] = (1.f - z0)*n0 + z0*ho.x;
                hnew[q][1] = (1.f - z1)*n1 + z1*ho.y;
            }
        }
        __syncthreads();    // all GEMM reads of sC done
#pragma unroll
        for (int q = 0; q < 6; ++q)
            *(float2*)(sC + rofs[q] + 64 + jr) = make_float2(hnew[q][0], hnew[q][1]);
        __syncthreads();

        // ---- decode (future steps only) ----
        if (!hist) {
            const int s = t - TT;
            if (w < 8) {
                const int q0 = w * 4;
#pragma unroll
                for (int rg = 0; rg < 3; ++rg) {
                    int r  = rg*32 + lane;
                    int rr = (r < ROWS) ? r : 0;
                    const float* hp = sC + rr*CS + 64;
                    float acc[4] = {0.f,0.f,0.f,0.f};
#pragma unroll 4
                    for (int kq = 0; kq < 16; ++kq) {
                        float4 hh = *(const float4*)(hp + kq*4);
#pragma unroll
                        for (int jj = 0; jj < 4; ++jj) {
                            const float4 wd = *(const float4*)(sWd1 + (q0+jj)*64 + kq*4);
                            float a = acc[jj];
                            a = fmaf(hh.x, wd.x, a); a = fmaf(hh.y, wd.y, a);
                            a = fmaf(hh.z, wd.z, a); a = fmaf(hh.w, wd.w, a);
                            acc[jj] = a;
                        }
                    }
                    if (r < ROWS) {
#pragma unroll
                        for (int jj = 0; jj < 4; ++jj)
                            sSup[r*SS + q0 + jj] = fmaxf(acc[jj] + sbd1[q0+jj], 0.f);
                    }
                }
            }
            __syncthreads();
            for (int e = tid; e < ROWS*FF; e += THREADS) {
                int r = e >> 2, f = e & 3;
                float v = sbd2[f];
#pragma unroll
                for (int q = 0; q < 32; ++q)
                    v = fmaf(sSup[r*SS + q], sWd2[f*32 + q], v);
                sX[e] = v;
                int bl = r / NNODES, n = r - bl*NNODES;
                out[(((size_t)(b0+bl)*FUT + s)*NNODES + n)*FF + f] = v;
            }
            __syncthreads();
        }
    }
}

extern "C" void kernel_launch(void* const* d_in, const int* in_sizes, int n_in,
                              void* d_out, int out_size) {
    const float* x_seq  = (const float*)d_in[0];
    const float* adj    = (const float*)d_in[1];
    const float* W_gcn  = (const float*)d_in[2];
    const float* b_gcn  = (const float*)d_in[3];
    const float* W_ih   = (const float*)d_in[4];
    const float* W_hh   = (const float*)d_in[5];
    const float* b_ih   = (const float*)d_in[6];
    const float* b_hh   = (const float*)d_in[7];
    const float* W_d1   = (const float*)d_in[8];
    const float* b_d1   = (const float*)d_in[9];
    const float* W_d2   = (const float*)d_in[10];
    const float* b_d2   = (const float*)d_in[11];
    float* out = (float*)d_out;

    const int smem_bytes = SMEM_FLOATS * (int)sizeof(float);
    cudaFuncSetAttribute(gwm_kernel, cudaFuncAttributeMaxDynamicSharedMemorySize, smem_bytes);
    gwm_kernel<<<BATCH / BPC, THREADS, smem_bytes>>>(
        x_seq, adj, W_gcn, b_gcn, W_ih, W_hh, b_ih, b_hh,
        W_d1, b_d1, W_d2, b_d2, out);
}

// round 17
// speedup vs baseline: 1.2628x; 1.2628x over previous
#include <cuda_runtime.h>
#include <cuda_bf16.h>
#include <cstdint>

typedef unsigned int u32;

#define TT      50
#define NNODES  23
#define FF      4
#define FUT     10
#define BPC     4
#define ROWS    92
#define THREADS 512

#define AST   136     // A k-stride (bf16 elems); 272B rows -> conflict-free frag loads
#define BRZST 136
#define BNST  72      // 144B rows
#define HS    68      // sH stride (f32)
#define D1S   36

// ---- smem byte offsets ----
#define O_AHI   0
#define O_ALO   (O_AHI   + 96*AST*2)
#define O_BRZHI (O_ALO   + 96*AST*2)
#define O_BRZLO (O_BRZHI + 128*BRZST*2)
#define O_BNIHI (O_BRZLO + 128*BRZST*2)
#define O_BNILO (O_BNIHI + 64*BNST*2)
#define O_BNHHI (O_BNILO + 64*BNST*2)
#define O_BNHLO (O_BNHHI + 64*BNST*2)
#define O_F32   (O_BNHLO + 64*BNST*2)
// f32-region float indices
#define F_H    0
#define F_ADJ  (F_H   + 96*HS)
#define F_X    (F_ADJ + ROWS*24)
#define F_WG   (F_X   + ROWS*4)
#define F_BG   (F_WG  + 256)
#define F_BRZ  (F_BG  + 64)
#define F_BIN  (F_BRZ + 128)
#define F_BHN  (F_BIN + 64)
#define F_BD1  (F_BHN + 64)
#define F_WD2  (F_BD1 + 32)
#define F_BD2  (F_WD2 + 128)
#define F_D1   (F_BD2 + 4)
#define F_END  (F_D1  + ROWS*D1S)
#define SMEM_BYTES (O_F32 + F_END*4)

__device__ __forceinline__ void mma16816(float c[4], u32 a0, u32 a1, u32 a2, u32 a3,
                                         u32 b0, u32 b1) {
    asm volatile(
        "mma.sync.aligned.m16n8k16.row.col.f32.bf16.bf16.f32 "
        "{%0,%1,%2,%3},{%4,%5,%6,%7},{%8,%9},{%0,%1,%2,%3};"
        : "+f"(c[0]), "+f"(c[1]), "+f"(c[2]), "+f"(c[3])
        : "r"(a0), "r"(a1), "r"(a2), "r"(a3), "r"(b0), "r"(b1));
}
__device__ __forceinline__ unsigned short bf16hi(float v) {
    return __bfloat16_as_ushort(__float2bfloat16(v));
}
__device__ __forceinline__ float sigmoidf_(float x) {
    return __fdividef(1.f, 1.f + __expf(-x));
}
__device__ __forceinline__ float tanhf_(float x) {
    return __fdividef(2.f, 1.f + __expf(-2.f * x)) - 1.f;
}

// One split-pass over K=128 (rz) + K=64 (n_i on spa half, n_h on h half).
__device__ __forceinline__ void gemm_pass(const char* __restrict__ smc,
                                          int aOff, int brzOff, int bniOff, int bnhOff,
                                          int mbase, int j0, int g, int t,
                                          float accR[3][4], float accZ[3][4],
                                          float accNi[3][4], float accNh[3][4]) {
#pragma unroll
    for (int kt = 0; kt < 8; ++kt) {
        const int kb = kt * 16;
        u32 A0[3], A1[3], A2[3], A3[3];
#pragma unroll
        for (int mt = 0; mt < 3; ++mt) {
            const int r0 = mbase + mt*16 + g;
            const char* ab = smc + aOff;
            A0[mt] = *(const u32*)(ab + (r0*AST     + kb + 2*t    )*2);
            A1[mt] = *(const u32*)(ab + ((r0+8)*AST + kb + 2*t    )*2);
            A2[mt] = *(const u32*)(ab + (r0*AST     + kb + 2*t + 8)*2);
            A3[mt] = *(const u32*)(ab + ((r0+8)*AST + kb + 2*t + 8)*2);
        }
        const char* brz = smc + brzOff;
        const u32 br0 = *(const u32*)(brz + ((j0+g)*BRZST    + kb + 2*t    )*2);
        const u32 br1 = *(const u32*)(brz + ((j0+g)*BRZST    + kb + 2*t + 8)*2);
        const u32 bz0 = *(const u32*)(brz + ((64+j0+g)*BRZST + kb + 2*t    )*2);
        const u32 bz1 = *(const u32*)(brz + ((64+j0+g)*BRZST + kb + 2*t + 8)*2);
#pragma unroll
        for (int mt = 0; mt < 3; ++mt) {
            mma16816(accR[mt], A0[mt], A1[mt], A2[mt], A3[mt], br0, br1);
            mma16816(accZ[mt], A0[mt], A1[mt], A2[mt], A3[mt], bz0, bz1);
        }
        if (kt < 4) {   // spa half -> i_n
            const char* bni = smc + bniOff;
            const u32 b0 = *(const u32*)(bni + ((j0+g)*BNST + kb + 2*t    )*2);
            const u32 b1 = *(const u32*)(bni + ((j0+g)*BNST + kb + 2*t + 8)*2);
#pragma unroll
            for (int mt = 0; mt < 3; ++mt)
                mma16816(accNi[mt], A0[mt], A1[mt], A2[mt], A3[mt], b0, b1);
        } else {        // h half -> h_n
            const int kb2 = kb - 64;
            const char* bnh = smc + bnhOff;
            const u32 b0 = *(const u32*)(bnh + ((j0+g)*BNST + kb2 + 2*t    )*2);
            const u32 b1 = *(const u32*)(bnh + ((j0+g)*BNST + kb2 + 2*t + 8)*2);
#pragma unroll
            for (int mt = 0; mt < 3; ++mt)
                mma16816(accNh[mt], A0[mt], A1[mt], A2[mt], A3[mt], b0, b1);
        }
    }
}

extern "C" __global__ void __launch_bounds__(THREADS, 1)
gwm_kernel(const float* __restrict__ x_seq, const float* __restrict__ adj_seq,
           const float* __restrict__ W_gcn, const float* __restrict__ b_gcn,
           const float* __restrict__ W_ih,  const float* __restrict__ W_hh,
           const float* __restrict__ b_ih,  const float* __restrict__ b_hh,
           const float* __restrict__ W_d1,  const float* __restrict__ b_d1,
           const float* __restrict__ W_d2,  const float* __restrict__ b_d2,
           float* __restrict__ out)
{
    extern __shared__ char smc[];
    float* smf  = (float*)(smc + O_F32);
    float* sH   = smf + F_H;
    float* sAdj = smf + F_ADJ;
    float* sX   = smf + F_X;
    float* sWg  = smf + F_WG;
    float* sbg  = smf + F_BG;
    float* sbrz = smf + F_BRZ;
    float* sbin = smf + F_BIN;
    float* sbhn = smf + F_BHN;
    float* sbd1 = smf + F_BD1;
    float* sWd2 = smf + F_WD2;
    float* sbd2 = smf + F_BD2;
    float* sD1  = smf + F_D1;

    const int tid  = threadIdx.x;
    const int w    = tid >> 5;
    const int lane = tid & 31;
    const int b0   = blockIdx.x * BPC;

    // warp tile: wm in {0,1} -> rows wm*48..+47 (3 m16 tiles); wj -> j block of 8
    const int wm = w >> 3;
    const int j0 = (w & 7) * 8;
    const int mbase = wm * 48;
    const int g = lane >> 2;     // 0..7
    const int t = lane & 3;      // 0..3

    // ---- one-time setup ----
    // Brz: n 0..127 (r rows 0..63, z rows 64..127), k 0..127 (spa|h)
    for (int e = tid; e < 128*128; e += THREADS) {
        int n = e >> 7, k = e & 127;
        float v = (k < 64) ? W_ih[n*64 + k] : W_hh[n*64 + (k-64)];
        unsigned short hi = bf16hi(v);
        *(unsigned short*)(smc + O_BRZHI + (n*BRZST + k)*2) = hi;
        *(unsigned short*)(smc + O_BRZLO + (n*BRZST + k)*2) =
            bf16hi(v - __bfloat162float(__ushort_as_bfloat16(hi)));
    }
    // Bni / Bnh: n-gate rows (W rows 128..191), k 0..63
    for (int e = tid; e < 64*64; e += THREADS) {
        int n = e >> 6, k = e & 63;
        float vi = W_ih[(128+n)*64 + k];
        float vh = W_hh[(128+n)*64 + k];
        unsigned short hi_i = bf16hi(vi), hi_h = bf16hi(vh);
        *(unsigned short*)(smc + O_BNIHI + (n*BNST + k)*2) = hi_i;
        *(unsigned short*)(smc + O_BNILO + (n*BNST + k)*2) =
            bf16hi(vi - __bfloat162float(__ushort_as_bfloat16(hi_i)));
        *(unsigned short*)(smc + O_BNHHI + (n*BNST + k)*2) = hi_h;
        *(unsigned short*)(smc + O_BNHLO + (n*BNST + k)*2) =
            bf16hi(vh - __bfloat162float(__ushort_as_bfloat16(hi_h)));
    }
    // zero A tiles (incl pad rows) and sH
    for (int e = tid; e < (2*96*AST*2)/4; e += THREADS) ((u32*)(smc + O_AHI))[e] = 0;
    for (int e = tid; e < 96*HS; e += THREADS) sH[e] = 0.f;
    for (int e = tid; e < 256; e += THREADS) sWg[e] = W_gcn[e];
    if (tid < 64)  sbg[tid]  = b_gcn[tid];
    if (tid < 128) sbrz[tid] = b_ih[tid] + b_hh[tid];
    if (tid >= 128 && tid < 192) sbin[tid-128] = b_ih[tid];
    if (tid >= 192 && tid < 256) sbhn[tid-192] = b_hh[tid-64];   // b_hh[128..191]
    if (tid < 32)  sbd1[tid] = b_d1[tid];
    if (tid < 128) sWd2[tid] = W_d2[tid];
    if (tid < 4)   sbd2[tid] = b_d2[tid];
    __syncthreads();

    for (int tstep = 0; tstep < TT + FUT; ++tstep) {
        const bool hist = (tstep < TT);
        if (hist) {
            for (int e = tid; e < BPC*NNODES*NNODES; e += THREADS) {
                int bl = e / (NNODES*NNODES);
                int i  = e - bl*(NNODES*NNODES);
                int n  = i / NNODES, m = i - n*NNODES;
                sAdj[(bl*NNODES + n)*24 + m] =
                    adj_seq[((size_t)(b0+bl)*TT + tstep)*(NNODES*NNODES) + i];
            }
            for (int e = tid; e < ROWS*FF; e += THREADS) {
                int bl = e / (NNODES*FF);
                int i  = e - bl*(NNODES*FF);
                sX[e] = x_seq[((size_t)(b0+bl)*TT + tstep)*(NNODES*FF) + i];
            }
            __syncthreads();
        }

        // ---- fused spatial: spa = relu((adj@x)@Wg^T + rowsum(adj)*bg) -> A spa cols ----
        for (int e = tid; e < ROWS*8; e += THREADS) {
            int r = e >> 3, jb8 = (e & 7) * 8;
            int bl = r / NNODES;
            const float* arow = sAdj + r*24;
            const float* xb   = sX + bl*NNODES*4;
            float y0 = 0.f, y1 = 0.f, y2 = 0.f, y3 = 0.f, s = 0.f;
#pragma unroll
            for (int m = 0; m < NNODES; ++m) {
                float a = arow[m];
                float4 xv = *(const float4*)(xb + m*4);
                y0 = fmaf(a, xv.x, y0); y1 = fmaf(a, xv.y, y1);
                y2 = fmaf(a, xv.z, y2); y3 = fmaf(a, xv.w, y3);
                s += a;
            }
#pragma unroll
            for (int jj = 0; jj < 8; jj += 2) {
                int j = jb8 + jj;
                float4 w0 = *(const float4*)(sWg + j*4);
                float4 w1 = *(const float4*)(sWg + (j+1)*4);
                float v0 = fmaf(y0, w0.x, fmaf(y1, w0.y, fmaf(y2, w0.z, fmaf(y3, w0.w, s*sbg[j]))));
                float v1 = fmaf(y0, w1.x, fmaf(y1, w1.y, fmaf(y2, w1.z, fmaf(y3, w1.w, s*sbg[j+1]))));
                v0 = fmaxf(v0, 0.f); v1 = fmaxf(v1, 0.f);
                unsigned short h0 = bf16hi(v0), h1 = bf16hi(v1);
                u32 hiw = ((u32)h1 << 16) | h0;
                u32 low = ((u32)bf16hi(v1 - __bfloat162float(__ushort_as_bfloat16(h1))) << 16)
                        |  (u32)bf16hi(v0 - __bfloat162float(__ushort_as_bfloat16(h0)));
                *(u32*)(smc + O_AHI + (r*AST + j)*2) = hiw;
                *(u32*)(smc + O_ALO + (r*AST + j)*2) = low;
            }
        }
        __syncthreads();   // A tiles ready

        // ---- gate GEMM on tensor cores: 3 split passes ----
        float accR[3][4], accZ[3][4], accNi[3][4], accNh[3][4];
#pragma unroll
        for (int mt = 0; mt < 3; ++mt)
#pragma unroll
            for (int i = 0; i < 4; ++i) {
                accR[mt][i] = 0.f; accZ[mt][i] = 0.f;
                accNi[mt][i] = 0.f; accNh[mt][i] = 0.f;
            }
        gemm_pass(smc, O_AHI, O_BRZHI, O_BNIHI, O_BNHHI, mbase, j0, g, t, accR, accZ, accNi, accNh);
        gemm_pass(smc, O_AHI, O_BRZLO, O_BNILO, O_BNHLO, mbase, j0, g, t, accR, accZ, accNi, accNh);
        gemm_pass(smc, O_ALO, O_BRZHI, O_BNIHI, O_BNHHI, mbase, j0, g, t, accR, accZ, accNi, accNh);

        // ---- GRU epilogue (registers; sH read is owner-exclusive) ----
        float hn[3][4];
#pragma unroll
        for (int mt = 0; mt < 3; ++mt) {
            const int r0 = mbase + mt*16 + g;
            const int ja = j0 + 2*t;
#pragma unroll
            for (int i = 0; i < 4; ++i) {
                const int row = (i < 2) ? r0 : r0 + 8;
                const int j   = ja + (i & 1);
                float rv = sigmoidf_(accR[mt][i] + sbrz[j]);
                float zv = sigmoidf_(accZ[mt][i] + sbrz[64+j]);
                float nv = tanhf_(accNi[mt][i] + sbin[j] + rv*(accNh[mt][i] + sbhn[j]));
                float ho = (row < ROWS) ? sH[row*HS + j] : 0.f;
                hn[mt][i] = (1.f - zv)*nv + zv*ho;
            }
        }
        __syncthreads();   // all mma reads of A h-cols complete
#pragma unroll
        for (int mt = 0; mt < 3; ++mt) {
            const int r0 = mbase + mt*16 + g;
            const int ja = j0 + 2*t;
#pragma unroll
            for (int i = 0; i < 4; ++i) {
                const int row = (i < 2) ? r0 : r0 + 8;
                const int j   = ja + (i & 1);
                if (row < ROWS) {
                    float v = hn[mt][i];
                    sH[row*HS + j] = v;
                    unsigned short hi = bf16hi(v);
                    *(unsigned short*)(smc + O_AHI + (row*AST + 64 + j)*2) = hi;
                    *(unsigned short*)(smc + O_ALO + (row*AST + 64 + j)*2) =
                        bf16hi(v - __bfloat162float(__ushort_as_bfloat16(hi)));
                }
            }
        }

        // ---- decode (future steps only) ----
        if (!hist) {
            const int s = tstep - TT;
            __syncthreads();   // sH visible to all
            if (w < 8) {
                const int q0 = w * 4;
#pragma unroll
                for (int rg = 0; rg < 3; ++rg) {
                    int r  = rg*32 + lane;
                    int rr = (r < ROWS) ? r : 0;
                    const float* hp = sH + rr*HS;
                    float acc[4] = {0.f, 0.f, 0.f, 0.f};
#pragma unroll 4
                    for (int kq = 0; kq < 16; ++kq) {
                        float4 hh = *(const float4*)(hp + kq*4);
#pragma unroll
                        for (int jj = 0; jj < 4; ++jj) {
                            const float4 wd = __ldg((const float4*)(W_d1 + (q0+jj)*64 + kq*4));
                            float a = acc[jj];
                            a = fmaf(hh.x, wd.x, a); a = fmaf(hh.y, wd.y, a);
                            a = fmaf(hh.z, wd.z, a); a = fmaf(hh.w, wd.w, a);
                            acc[jj] = a;
                        }
                    }
                    if (r < ROWS) {
#pragma unroll
                        for (int jj = 0; jj < 4; ++jj)
                            sD1[r*D1S + q0 + jj] = fmaxf(acc[jj] + sbd1[q0+jj], 0.f);
                    }
                }
            }
            __syncthreads();
            for (int e = tid; e < ROWS*FF; e += THREADS) {
                int r = e >> 2, f = e & 3;
                float v = sbd2[f];
#pragma unroll
                for (int q = 0; q < 32; ++q)
                    v = fmaf(sD1[r*D1S + q], sWd2[f*32 + q], v);
                sX[e] = v;
                int bl = r / NNODES, n = r - bl*NNODES;
                out[(((size_t)(b0+bl)*FUT + s)*NNODES + n)*FF + f] = v;
            }
            __syncthreads();
        }
    }
}

extern "C" void kernel_launch(void* const* d_in, const int* in_sizes, int n_in,
                              void* d_out, int out_size) {
    const float* x_seq  = (const float*)d_in[0];
    const float* adj    = (const float*)d_in[1];
    const float* W_gcn  = (const float*)d_in[2];
    const float* b_gcn  = (const float*)d_in[3];
    const float* W_ih   = (const float*)d_in[4];
    const float* W_hh   = (const float*)d_in[5];
    const float* b_ih   = (const float*)d_in[6];
    const float* b_hh   = (const float*)d_in[7];
    const float* W_d1   = (const float*)d_in[8];
    const float* b_d1   = (const float*)d_in[9];
    const float* W_d2   = (const float*)d_in[10];
    const float* b_d2   = (const float*)d_in[11];
    float* out = (float*)d_out;

    cudaFuncSetAttribute(gwm_kernel, cudaFuncAttributeMaxDynamicSharedMemorySize, SMEM_BYTES);
    gwm_kernel<<<2048 / BPC, THREADS, SMEM_BYTES>>>(
        x_seq, adj, W_gcn, b_gcn, W_ih, W_hh, b_ih, b_hh,
        W_d1, b_d1, W_d2, b_d2, out);
}